// round 16
// baseline (speedup 1.0000x reference)
#include <cuda_runtime.h>
#include <cuda_fp16.h>
#include <cstdint>
#include <math.h>

#define BB 4
#define SS 4096
#define DD 1024
#define DQK 64
#define MM (BB * SS)          // 16384 rows

// ---------------- scratch (alloc-free: __device__ globals) ----------------
static __device__ __half g_Ph[(size_t)BB * SS * SS];    // 134 MB unnormalized exp(s) fp16
static __device__ __half g_Vh[(size_t)MM * DD];         // enc hi fp16 (also proj A)
static __device__ __half g_Vl[(size_t)MM * DD];         // enc lo fp16 (proj only)
static __device__ __half g_Wh[128 * DD];                // W concat (Q|K) hi
static __device__ __half g_Wl[128 * DD];                // W concat lo
static __device__ __half g_Qh[(size_t)MM * DQK];        // Q hi (pre-scaled 1/8)
static __device__ __half g_Ql[(size_t)MM * DQK];
static __device__ __half g_Kh[(size_t)MM * DQK];
static __device__ __half g_Kl[(size_t)MM * DQK];
static __device__ float  g_l[MM];                       // row sums (atomic)

// fast exp on the fma/alu pipes (no MUFU)
__device__ __forceinline__ float fexp(float x) {
    float t = fmaxf(x, -80.0f) * 1.44269504f;
    float f = rintf(t);
    float r = t - f;
    float p = 1.0f + r * (0.69314718f + r * (0.24022651f + r * (0.05550411f
                  + r * (0.00961813f + r * 0.00133336f))));
    int e = (int)f;
    uint32_t bits = (uint32_t)(e + 127) << 23;
    return p * __uint_as_float(bits);
}

// ---------------- shared PTX helpers ----------------
__device__ __forceinline__ void cp16(uint32_t dst, const void* src) {
    asm volatile(
        "{\n\t"
        ".reg .u64 gp;\n\t"
        "cvta.to.global.u64 gp, %1;\n\t"
        "cp.async.ca.shared.global [%0], [gp], 16;\n\t"
        "}"
        :: "r"(dst), "l"(src) : "memory");
}
__device__ __forceinline__ void cpcommit() {
    asm volatile("cp.async.commit_group;" ::: "memory");
}
__device__ __forceinline__ void cpwait0() {
    asm volatile("cp.async.wait_group 0;" ::: "memory");
}
__device__ __forceinline__ void cpwait1() {
    asm volatile("cp.async.wait_group 1;" ::: "memory");
}

__device__ __forceinline__ void ldsm4(uint32_t* r, const void* p) {
    uint32_t a = (uint32_t)__cvta_generic_to_shared(p);
    asm volatile("ldmatrix.sync.aligned.m8n8.x4.shared.b16 {%0,%1,%2,%3}, [%4];"
                 : "=r"(r[0]), "=r"(r[1]), "=r"(r[2]), "=r"(r[3])
                 : "r"(a));
}
__device__ __forceinline__ void ldsm4t(uint32_t* r, const void* p) {
    uint32_t a = (uint32_t)__cvta_generic_to_shared(p);
    asm volatile("ldmatrix.sync.aligned.m8n8.x4.trans.shared.b16 {%0,%1,%2,%3}, [%4];"
                 : "=r"(r[0]), "=r"(r[1]), "=r"(r[2]), "=r"(r[3])
                 : "r"(a));
}
__device__ __forceinline__ void mma_f16(float* c, const uint32_t* a,
                                        uint32_t b0, uint32_t b1) {
    asm volatile(
        "mma.sync.aligned.m16n8k16.row.col.f32.f16.f16.f32 "
        "{%0,%1,%2,%3}, {%4,%5,%6,%7}, {%8,%9}, {%0,%1,%2,%3};"
        : "+f"(c[0]), "+f"(c[1]), "+f"(c[2]), "+f"(c[3])
        : "r"(a[0]), "r"(a[1]), "r"(a[2]), "r"(a[3]), "r"(b0), "r"(b1));
}

// =====================================================================
// Kernel 1: enc -> fp16 hi/lo  (also zeroes g_l)
// =====================================================================
__global__ __launch_bounds__(256) void vconv_kernel(const float* __restrict__ enc) {
    const int gtid = blockIdx.x * 256 + threadIdx.x;
    if (gtid < MM) { g_l[gtid] = 0.0f; }
    const size_t n = (size_t)MM * DD;
    size_t i = ((size_t)gtid) * 4;
    const size_t step = (size_t)gridDim.x * 256 * 4;
    for (; i < n; i += step) {
        float4 v = *(const float4*)&enc[i];
        __half2 h01 = __floats2half2_rn(v.x, v.y);
        __half2 h23 = __floats2half2_rn(v.z, v.w);
        float2 r01 = __half22float2(h01);
        float2 r23 = __half22float2(h23);
        *(__half2*)&g_Vh[i] = h01;
        *(__half2*)&g_Vh[i + 2] = h23;
        *(__half2*)&g_Vl[i] = __floats2half2_rn(v.x - r01.x, v.y - r01.y);
        *(__half2*)&g_Vl[i + 2] = __floats2half2_rn(v.z - r23.x, v.w - r23.y);
    }
}

// =====================================================================
// Kernel 2: W -> fp16 hi/lo concat [128 rows: 0-63 Wq, 64-127 Wk]
// =====================================================================
__global__ __launch_bounds__(256) void wconv_kernel(const float* __restrict__ Wq,
                                                    const float* __restrict__ Wk) {
    int i = blockIdx.x * 256 + threadIdx.x;
    const int n = 128 * DD;
    for (; i < n; i += gridDim.x * 256) {
        int row = i >> 10;
        int c = i & 1023;
        float v = (row < 64) ? Wq[row * DD + c] : Wk[(row - 64) * DD + c];
        __half h = __float2half_rn(v);
        g_Wh[i] = h;
        g_Wl[i] = __float2half_rn(v - __half2float(h));
    }
}

// =====================================================================
// Kernel 3: tensor proj. [Q|K](16384x128) = enc(16384x1024) @ Wcat^T.
// =====================================================================
#define PJSTR 40
#define PROJ_SMEM_BYTES 81920

__device__ __forceinline__ void proj_load(uint32_t smb, int st, int tid,
                                          int m0, int k0) {
    const int row = tid >> 1;
    const int seg = (tid & 1) * 16;
    uint32_t dA = smb + (uint32_t)((st * 5120 + row * PJSTR + seg) * 2);
    const __half* sa = &g_Vh[(size_t)(m0 + row) * DD + k0 + seg];
    cp16(dA, sa);
    cp16(dA + 16, sa + 8);
    uint32_t dAl = dA + 10240 * 2;
    const __half* sal = &g_Vl[(size_t)(m0 + row) * DD + k0 + seg];
    cp16(dAl, sal);
    cp16(dAl + 16, sal + 8);
    uint32_t dB = smb + (uint32_t)((20480 + st * 5120 + row * PJSTR + seg) * 2);
    const __half* sb = &g_Wh[row * DD + k0 + seg];
    cp16(dB, sb);
    cp16(dB + 16, sb + 8);
    uint32_t dBl = dB + 10240 * 2;
    const __half* sbl = &g_Wl[row * DD + k0 + seg];
    cp16(dBl, sbl);
    cp16(dBl + 16, sbl + 8);
}

__global__ __launch_bounds__(256) void proj_kernel() {
    extern __shared__ __half sm[];
    const uint32_t smb = (uint32_t)__cvta_generic_to_shared((void*)sm);
    const int m0 = blockIdx.x * 128;
    const int tid = threadIdx.x;
    const int lane = tid & 31;
    const int wid = tid >> 5;
    const int wm = (wid & 3) * 32;
    const int wn = (wid >> 2) * 64;

    float acc[2][8][4];
#pragma unroll
    for (int i = 0; i < 2; i++)
#pragma unroll
        for (int j = 0; j < 8; j++)
#pragma unroll
            for (int q = 0; q < 4; q++) acc[i][j][q] = 0.0f;

    proj_load(smb, 0, tid, m0, 0);
    cpcommit();

    const int nk = DD / 32;
    for (int kt = 0; kt < nk; kt++) {
        const int st = kt & 1;
        if (kt + 1 < nk) {
            proj_load(smb, st ^ 1, tid, m0, (kt + 1) * 32);
            cpcommit();
            cpwait1();
        } else {
            cpwait0();
        }
        __syncthreads();

        const __half* sAh = sm + st * 5120;
        const __half* sAl = sm + 10240 + st * 5120;
        const __half* sBh = sm + 20480 + st * 5120;
        const __half* sBl = sm + 30720 + st * 5120;

#pragma unroll
        for (int k16 = 0; k16 < 2; k16++) {
            const int kc = k16 * 16 + (lane >> 4) * 8;
            const int arow = lane & 15;
            uint32_t ah0[4], ah1[4], al0[4], al1[4];
            ldsm4(ah0, sAh + (wm + arow) * PJSTR + kc);
            ldsm4(ah1, sAh + (wm + 16 + arow) * PJSTR + kc);
            ldsm4(al0, sAl + (wm + arow) * PJSTR + kc);
            ldsm4(al1, sAl + (wm + 16 + arow) * PJSTR + kc);
#pragma unroll
            for (int n16 = 0; n16 < 4; n16++) {
                uint32_t bh[4], bl[4];
                ldsm4(bh, sBh + (wn + n16 * 16 + arow) * PJSTR + kc);
                ldsm4(bl, sBl + (wn + n16 * 16 + arow) * PJSTR + kc);
                float* c0 = acc[0][n16 * 2];
                float* c1 = acc[0][n16 * 2 + 1];
                float* c2 = acc[1][n16 * 2];
                float* c3 = acc[1][n16 * 2 + 1];
                mma_f16(c0, ah0, bh[0], bh[2]);
                mma_f16(c0, al0, bh[0], bh[2]);
                mma_f16(c0, ah0, bl[0], bl[2]);
                mma_f16(c1, ah0, bh[1], bh[3]);
                mma_f16(c1, al0, bh[1], bh[3]);
                mma_f16(c1, ah0, bl[1], bl[3]);
                mma_f16(c2, ah1, bh[0], bh[2]);
                mma_f16(c2, al1, bh[0], bh[2]);
                mma_f16(c2, ah1, bl[0], bl[2]);
                mma_f16(c3, ah1, bh[1], bh[3]);
                mma_f16(c3, al1, bh[1], bh[3]);
                mma_f16(c3, ah1, bl[1], bl[3]);
            }
        }
        __syncthreads();
    }

    const float scale = (wn == 0) ? 0.125f : 1.0f;
#pragma unroll
    for (int mi = 0; mi < 2; mi++) {
#pragma unroll
        for (int h = 0; h < 2; h++) {
            const int m = m0 + wm + mi * 16 + (lane >> 2) + h * 8;
#pragma unroll
            for (int nb = 0; nb < 8; nb++) {
                const int col = wn + nb * 8 + (lane & 3) * 2;
                float v0 = acc[mi][nb][h * 2 + 0] * scale;
                float v1 = acc[mi][nb][h * 2 + 1] * scale;
                __half2 hi = __floats2half2_rn(v0, v1);
                float2 hf = __half22float2(hi);
                __half2 lo = __floats2half2_rn(v0 - hf.x, v1 - hf.y);
                if (wn == 0) {
                    *(__half2*)&g_Qh[(size_t)m * DQK + col] = hi;
                    *(__half2*)&g_Ql[(size_t)m * DQK + col] = lo;
                } else {
                    *(__half2*)&g_Kh[(size_t)m * DQK + col - 64] = hi;
                    *(__half2*)&g_Kl[(size_t)m * DQK + col - 64] = lo;
                }
            }
        }
    }
}

// =====================================================================
// Kernel 4: tensor score, ONE 128x128 causal tile per block.
// =====================================================================
#define SCSTR 72
#define SCORE_SMEM_BYTES 73728

__global__ __launch_bounds__(256) void score_kernel() {
    extern __shared__ __half sm[];
    const uint32_t smb = (uint32_t)__cvta_generic_to_shared((void*)sm);
    const int b = blockIdx.y;
    const int t = blockIdx.x;
    int qt = (int)((sqrtf(8.0f * (float)t + 1.0f) - 1.0f) * 0.5f);
    while ((qt + 1) * (qt + 2) / 2 <= t) { qt++; }
    while (qt * (qt + 1) / 2 > t) { qt--; }
    const int kt = t - qt * (qt + 1) / 2;

    const int q0 = qt * 128;
    const int k0 = kt * 128;
    const int gq0 = b * SS + q0;
    const int gk0 = b * SS + k0;
    const int tid = threadIdx.x;
    const int lane = tid & 31;
    const int wid = tid >> 5;
    const int wm = (wid & 3) * 32;
    const int wn = (wid >> 2) * 64;

    {
        const int row = tid >> 1;
        const int seg = (tid & 1) * 32;
        uint32_t d0 = smb + (uint32_t)((row * SCSTR + seg) * 2);
        const __half* s0 = &g_Qh[(size_t)(gq0 + row) * DQK + seg];
        cp16(d0, s0); cp16(d0 + 16, s0 + 8); cp16(d0 + 32, s0 + 16); cp16(d0 + 48, s0 + 24);
        uint32_t d1 = d0 + 9216 * 2;
        const __half* s1 = &g_Ql[(size_t)(gq0 + row) * DQK + seg];
        cp16(d1, s1); cp16(d1 + 16, s1 + 8); cp16(d1 + 32, s1 + 16); cp16(d1 + 48, s1 + 24);
        uint32_t d2 = d0 + 18432 * 2;
        const __half* s2 = &g_Kh[(size_t)(gk0 + row) * DQK + seg];
        cp16(d2, s2); cp16(d2 + 16, s2 + 8); cp16(d2 + 32, s2 + 16); cp16(d2 + 48, s2 + 24);
        uint32_t d3 = d0 + 27648 * 2;
        const __half* s3 = &g_Kl[(size_t)(gk0 + row) * DQK + seg];
        cp16(d3, s3); cp16(d3 + 16, s3 + 8); cp16(d3 + 32, s3 + 16); cp16(d3 + 48, s3 + 24);
    }
    cpcommit();
    cpwait0();
    __syncthreads();

    const __half* sQh = sm;
    const __half* sQl = sm + 9216;
    const __half* sKh = sm + 18432;
    const __half* sKl = sm + 27648;

    float acc[2][8][4];
#pragma unroll
    for (int i = 0; i < 2; i++)
#pragma unroll
        for (int j = 0; j < 8; j++)
#pragma unroll
            for (int q = 0; q < 4; q++) acc[i][j][q] = 0.0f;

#pragma unroll
    for (int k16 = 0; k16 < 4; k16++) {
        const int kc = k16 * 16 + (lane >> 4) * 8;
        const int arow = lane & 15;
        uint32_t ah0[4], ah1[4], al0[4], al1[4];
        ldsm4(ah0, sQh + (wm + arow) * SCSTR + kc);
        ldsm4(ah1, sQh + (wm + 16 + arow) * SCSTR + kc);
        ldsm4(al0, sQl + (wm + arow) * SCSTR + kc);
        ldsm4(al1, sQl + (wm + 16 + arow) * SCSTR + kc);
#pragma unroll
        for (int n16 = 0; n16 < 4; n16++) {
            uint32_t bh[4], bl[4];
            ldsm4(bh, sKh + (wn + n16 * 16 + arow) * SCSTR + kc);
            ldsm4(bl, sKl + (wn + n16 * 16 + arow) * SCSTR + kc);
            float* c0 = acc[0][n16 * 2];
            float* c1 = acc[0][n16 * 2 + 1];
            float* c2 = acc[1][n16 * 2];
            float* c3 = acc[1][n16 * 2 + 1];
            mma_f16(c0, ah0, bh[0], bh[2]);
            mma_f16(c0, al0, bh[0], bh[2]);
            mma_f16(c0, ah0, bl[0], bl[2]);
            mma_f16(c1, ah0, bh[1], bh[3]);
            mma_f16(c1, al0, bh[1], bh[3]);
            mma_f16(c1, ah0, bl[1], bl[3]);
            mma_f16(c2, ah1, bh[0], bh[2]);
            mma_f16(c2, al1, bh[0], bh[2]);
            mma_f16(c2, ah1, bl[0], bl[2]);
            mma_f16(c3, ah1, bh[1], bh[3]);
            mma_f16(c3, al1, bh[1], bh[3]);
            mma_f16(c3, ah1, bl[1], bl[3]);
        }
    }

    float rowsum[2][2];
    rowsum[0][0] = 0.0f; rowsum[0][1] = 0.0f;
    rowsum[1][0] = 0.0f; rowsum[1][1] = 0.0f;

#pragma unroll
    for (int mi = 0; mi < 2; mi++) {
        const int r0 = q0 + wm + mi * 16 + (lane >> 2);
        const int r1 = r0 + 8;
#pragma unroll
        for (int nb = 0; nb < 8; nb++) {
            const int kcol = k0 + wn + nb * 8 + (lane & 3) * 2;
            float s0 = (kcol <= r0) ? acc[mi][nb][0] : -1e9f;
            float s1 = (kcol + 1 <= r0) ? acc[mi][nb][1] : -1e9f;
            float s2 = (kcol <= r1) ? acc[mi][nb][2] : -1e9f;
            float s3 = (kcol + 1 <= r1) ? acc[mi][nb][3] : -1e9f;
            float p0 = fexp(s0);
            float p1 = fexp(s1);
            float p2 = fexp(s2);
            float p3 = fexp(s3);
            rowsum[mi][0] += p0 + p1;
            rowsum[mi][1] += p2 + p3;
            *(__half2*)&g_Ph[((size_t)(b * SS + r0)) * SS + kcol] =
                __floats2half2_rn(p0, p1);
            *(__half2*)&g_Ph[((size_t)(b * SS + r1)) * SS + kcol] =
                __floats2half2_rn(p2, p3);
        }
    }

#pragma unroll
    for (int mi = 0; mi < 2; mi++) {
#pragma unroll
        for (int h = 0; h < 2; h++) {
            float v = rowsum[mi][h];
            v += __shfl_xor_sync(0xffffffffu, v, 1);
            v += __shfl_xor_sync(0xffffffffu, v, 2);
            if ((lane & 3) == 0) {
                const int row = q0 + wm + mi * 16 + (lane >> 2) + h * 8;
                atomicAdd(&g_l[b * SS + row], v);
            }
        }
    }
}

// =====================================================================
// Kernel 5: tensor PV, block tile 128x256, warp tile m64xn64,
// 3-stage cp.async ring.  O = (P~ @ Vh) * 1/l.
// smem halfs: P[st] at st*5120 (st 0..2), V[st] at 15360 + st*8448
// =====================================================================
#define PSTR 40
#define VSTR 264
#define PV_SMEM_BYTES 81408

__device__ __forceinline__ void pv_load_stage(uint32_t smb, int st, int tid,
                                              const __half* gP,
                                              const __half* gVh) {
    const int pr = tid >> 1;
    const int pc = (tid & 1) * 16;
    uint32_t dP = smb + (uint32_t)((st * 5120 + pr * PSTR + pc) * 2);
    cp16(dP, gP + (size_t)pr * SS + pc);
    cp16(dP + 16, gP + (size_t)pr * SS + pc + 8);
    const int vk = tid >> 3;
    const int vc = (tid & 7) * 32;
    uint32_t dV = smb + (uint32_t)(((15360 + st * 8448) + vk * VSTR + vc) * 2);
    const __half* s = gVh + (size_t)vk * DD + vc;
    cp16(dV, s);
    cp16(dV + 16, s + 8);
    cp16(dV + 32, s + 16);
    cp16(dV + 48, s + 24);
}

__global__ __launch_bounds__(256, 1) void pv_kernel(float* __restrict__ out) {
    extern __shared__ __half sm[];
    const int ct = blockIdx.x;                            // 0..3 (256-col tiles)
    const int rt = (int)gridDim.y - 1 - (int)blockIdx.y;  // heavy first
    const int b  = blockIdx.z;
    const int q0 = rt * 128;
    const int c0 = ct * 256;
    const int tid = threadIdx.x;
    const int lane = tid & 31;
    const int wid = tid >> 5;
    const int wm = (wid & 1) * 64;       // 2 warp rows
    const int wn = (wid >> 1) * 64;      // 4 warp cols

    const uint32_t smb = (uint32_t)__cvta_generic_to_shared((void*)sm);

    float acc[4][8][4];
#pragma unroll
    for (int i = 0; i < 4; i++)
#pragma unroll
        for (int j = 0; j < 8; j++)
#pragma unroll
            for (int q = 0; q < 4; q++) acc[i][j][q] = 0.0f;

    const __half* gPbase = &g_Ph[((size_t)(b * SS + q0)) * SS];
    const __half* gVhbase = &g_Vh[((size_t)(b * SS)) * DD + c0];

    const int nk = (rt + 1) * 4;   // k32 steps (>= 4)

    pv_load_stage(smb, 0, tid, gPbase, gVhbase);
    cpcommit();
    pv_load_stage(smb, 1, tid, gPbase + 32, gVhbase + (size_t)32 * DD);
    cpcommit();

    int st = 0;
    for (int kt = 0; kt < nk; kt++) {
        if (kt + 1 < nk) { cpwait1(); } else { cpwait0(); }
        __syncthreads();

        // issue stage kt+2 (buffer (kt+2)%3 was consumed in iter kt-1)
        if (kt + 2 < nk) {
            int st2 = st + 2; if (st2 >= 3) st2 -= 3;
            const int k2 = (kt + 2) * 32;
            pv_load_stage(smb, st2, tid, gPbase + k2,
                          gVhbase + (size_t)k2 * DD);
            cpcommit();
        }

        const __half* sP = sm + st * 5120;
        const __half* sV = sm + 15360 + st * 8448;

#pragma unroll
        for (int s16 = 0; s16 < 2; s16++) {
            const int arow = lane & 15;
            const int ak = s16 * 16 + (lane >> 4) * 8;
            uint32_t a[4][4];
#pragma unroll
            for (int mi = 0; mi < 4; mi++) {
                ldsm4(a[mi], sP + (wm + mi * 16 + arow) * PSTR + ak);
            }
#pragma unroll
            for (int nb = 0; nb < 4; nb++) {
                const int bofs = (s16 * 16 + (lane & 15)) * VSTR
                               + wn + nb * 16 + (lane >> 4) * 8;
                uint32_t bh[4];
                ldsm4t(bh, sV + bofs);
#pragma unroll
                for (int mi = 0; mi < 4; mi++) {
                    mma_f16(acc[mi][nb * 2],     a[mi], bh[0], bh[1]);
                    mma_f16(acc[mi][nb * 2 + 1], a[mi], bh[2], bh[3]);
                }
            }
        }
        __syncthreads();
        st = st + 1; if (st >= 3) st = 0;
    }

    // epilogue: normalize by 1/l, store fp32
#pragma unroll
    for (int mi = 0; mi < 4; mi++) {
        const int r0 = q0 + wm + mi * 16 + (lane >> 2);
        const float il0 = __fdividef(1.0f, g_l[b * SS + r0]);
        const float il1 = __fdividef(1.0f, g_l[b * SS + r0 + 8]);
#pragma unroll
        for (int nb8 = 0; nb8 < 8; nb8++) {
            const int cc = c0 + wn + nb8 * 8 + (lane & 3) * 2;
            float2* o0 = (float2*)&out[((size_t)(b * SS + r0)) * DD + cc];
            float2* o1 = (float2*)&out[((size_t)(b * SS + r0 + 8)) * DD + cc];
            o0->x = acc[mi][nb8][0] * il0;
            o0->y = acc[mi][nb8][1] * il0;
            o1->x = acc[mi][nb8][2] * il1;
            o1->y = acc[mi][nb8][3] * il1;
        }
    }
}

// =====================================================================
extern "C" void kernel_launch(void* const* d_in, const int* in_sizes, int n_in,
                              void* d_out, int out_size) {
    (void)in_sizes; (void)n_in; (void)out_size;
    const float* enc = (const float*)d_in[0];
    const float* Wq  = (const float*)d_in[1];
    const float* Wk  = (const float*)d_in[2];
    float* out = (float*)d_out;

    cudaFuncSetAttribute(proj_kernel, cudaFuncAttributeMaxDynamicSharedMemorySize,
                         PROJ_SMEM_BYTES);
    cudaFuncSetAttribute(score_kernel, cudaFuncAttributeMaxDynamicSharedMemorySize,
                         SCORE_SMEM_BYTES);
    cudaFuncSetAttribute(pv_kernel, cudaFuncAttributeMaxDynamicSharedMemorySize,
                         PV_SMEM_BYTES);

    vconv_kernel<<<1024, 256>>>(enc);
    wconv_kernel<<<128, 256>>>(Wq, Wk);
    proj_kernel<<<MM / 128, 256, PROJ_SMEM_BYTES>>>();
    score_kernel<<<dim3((SS / 128) * (SS / 128 + 1) / 2, BB), 256, SCORE_SMEM_BYTES>>>();
    pv_kernel<<<dim3(DD / 256, SS / 128, BB), 256, PV_SMEM_BYTES>>>(out);
}